// round 2
// baseline (speedup 1.0000x reference)
#include <cuda_runtime.h>
#include <math.h>

// ---------------- problem constants ----------------
constexpr int kB   = 8;
constexpr int kN   = 2048;
constexpr int kM   = 512;
constexpr int kCIN = 256;
constexpr int kCFP = 128;
constexpr int kC   = 128;   // C_OUT
constexpr int kCG  = 512;
constexpr int kH   = 8;
constexpr int kD   = 16;    // head dim

// ---------------- scratch (no allocation allowed) ----------------
__device__ float g_interp[kB * kCIN * kN];
__device__ float g_h1    [kB * kCIN * kN];
__device__ float g_nf    [kB * kCFP * kN];
__device__ float g_qf    [kB * kC   * kN];
__device__ float g_vf    [kB * kC   * kN];
__device__ float g_Q     [kB * kC   * kN];
__device__ float g_K     [kB * kC   * kN];
__device__ float g_V     [kB * kC   * kN];
__device__ float g_O     [kB * kC   * kN];
__device__ float g_y     [kB * kC   * kN];
__device__ float g_gb    [kB * kC];
__device__ int   g_idx   [kB * kN * 3];
__device__ float g_w     [kB * kN * 3];

// ---------------- fast exp2 (x <= 0), poly degree 6, err ~2e-5 ----------------
__device__ __forceinline__ float exp2p(float x) {
    x = fmaxf(x, -126.0f);
    float fl = floorf(x);
    float f  = x - fl;                 // [0,1)
    float p  = 1.54035304e-4f;
    p = fmaf(p, f, 1.33335581e-3f);
    p = fmaf(p, f, 9.61812911e-3f);
    p = fmaf(p, f, 5.55041087e-2f);
    p = fmaf(p, f, 2.40226507e-1f);
    p = fmaf(p, f, 6.93147181e-1f);
    p = fmaf(p, f, 1.0f);
    int e = (int)fl;
    float sc = __int_as_float((e + 127) << 23);
    return p * sc;
}

// ---------------- three_nn: 3 nearest of M=512 per upsampled point ----------------
__global__ __launch_bounds__(256) void knn_kernel(
    const float* __restrict__ up_xyz, const float* __restrict__ xyz,
    int* __restrict__ idxo, float* __restrict__ wo)
{
    __shared__ float sx[kM * 3];
    const int b = blockIdx.y;
    for (int i = threadIdx.x; i < kM * 3; i += 256) sx[i] = xyz[b * kM * 3 + i];
    __syncthreads();

    const int n = blockIdx.x * 256 + threadIdx.x;
    const float px = up_xyz[(b * kN + n) * 3 + 0];
    const float py = up_xyz[(b * kN + n) * 3 + 1];
    const float pz = up_xyz[(b * kN + n) * 3 + 2];

    float d0 = 1e30f, d1 = 1e30f, d2 = 1e30f;
    int   i0 = 0,     i1 = 0,     i2 = 0;
    for (int m = 0; m < kM; m++) {
        float dx = sx[m * 3 + 0] - px;
        float dy = sx[m * 3 + 1] - py;
        float dz = sx[m * 3 + 2] - pz;
        float d  = dx * dx + dy * dy + dz * dz;
        if (d < d2) {
            if (d < d1) {
                if (d < d0) { d2 = d1; i2 = i1; d1 = d0; i1 = i0; d0 = d; i0 = m; }
                else        { d2 = d1; i2 = i1; d1 = d;  i1 = m; }
            } else          { d2 = d;  i2 = m; }
        }
    }
    d0 = fmaxf(d0, 1e-10f); d1 = fmaxf(d1, 1e-10f); d2 = fmaxf(d2, 1e-10f);
    float r0 = 1.0f / d0, r1 = 1.0f / d1, r2 = 1.0f / d2;
    float s  = r0 + r1 + r2;
    const int base = (b * kN + n) * 3;
    idxo[base] = i0; idxo[base + 1] = i1; idxo[base + 2] = i2;
    wo[base] = r0 / s; wo[base + 1] = r1 / s; wo[base + 2] = r2 / s;
}

// ---------------- inverse-distance interpolation ----------------
__global__ void interp_kernel(
    const float* __restrict__ feat, const int* __restrict__ idx3,
    const float* __restrict__ w3, float* __restrict__ out)
{
    const int b = blockIdx.z, c = blockIdx.y;
    const int n = blockIdx.x * 256 + threadIdx.x;
    const float* f = feat + ((size_t)b * kCIN + c) * kM;
    const int base = (b * kN + n) * 3;
    const int j0 = idx3[base], j1 = idx3[base + 1], j2 = idx3[base + 2];
    const float w0 = w3[base], w1 = w3[base + 1], w2 = w3[base + 2];
    out[((size_t)b * kCIN + c) * kN + n] = w0 * f[j0] + w1 * f[j1] + w2 * f[j2];
}

// ---------------- generic tiled GEMM + CBL/add epilogue ----------------
// Y[b,oc,n] = act( (sum_ic W[oc,ic]*X[b,ic,n] + bias[oc]) * gamma[oc]/sqrt(1+eps) + beta[oc] + add[b,oc,n] )
__global__ __launch_bounds__(256) void gemm_cbl(
    const float* __restrict__ W, const float* __restrict__ X, float* __restrict__ Y,
    const float* __restrict__ bias, const float* __restrict__ gamma,
    const float* __restrict__ beta, const float* __restrict__ add,
    int OC, int IC, int relu)
{
    __shared__ float Ws[16][64];
    __shared__ float Xs[16][64];
    const int b   = blockIdx.z;
    const int n0  = blockIdx.x * 64;
    const int oc0 = blockIdx.y * 64;
    const float* Xb = X + (size_t)b * IC * kN;
    const int tid = threadIdx.x;
    const int tx = tid & 15, ty = tid >> 4;

    float acc[4][4];
#pragma unroll
    for (int i = 0; i < 4; i++)
#pragma unroll
        for (int j = 0; j < 4; j++) acc[i][j] = 0.0f;

    for (int k0 = 0; k0 < IC; k0 += 16) {
#pragma unroll
        for (int r = 0; r < 4; r++) {
            int e = tid + r * 256;
            Ws[e & 15][e >> 4] = W[(size_t)(oc0 + (e >> 4)) * IC + k0 + (e & 15)];
        }
#pragma unroll
        for (int r = 0; r < 4; r++) {
            int e = tid + r * 256;
            Xs[e >> 6][e & 63] = Xb[(size_t)(k0 + (e >> 6)) * kN + n0 + (e & 63)];
        }
        __syncthreads();
#pragma unroll
        for (int kk = 0; kk < 16; kk++) {
            const float4 wv = *(const float4*)&Ws[kk][ty * 4];
            const float4 xv = *(const float4*)&Xs[kk][tx * 4];
            const float wr[4] = {wv.x, wv.y, wv.z, wv.w};
            const float xr[4] = {xv.x, xv.y, xv.z, xv.w};
#pragma unroll
            for (int i = 0; i < 4; i++)
#pragma unroll
                for (int j = 0; j < 4; j++)
                    acc[i][j] = fmaf(wr[i], xr[j], acc[i][j]);
        }
        __syncthreads();
    }

    const float rs = rsqrtf(1.0f + 1e-5f);
#pragma unroll
    for (int i = 0; i < 4; i++) {
        const int oc = oc0 + ty * 4 + i;
        const float bi = bias  ? bias[oc]        : 0.0f;
        const float sc = gamma ? gamma[oc] * rs  : 1.0f;
        const float bb = gamma ? beta[oc]        : 0.0f;
#pragma unroll
        for (int j = 0; j < 4; j++) {
            const int n = n0 + tx * 4 + j;
            float v = fmaf(acc[i][j] + bi, sc, bb);
            if (add)  v += add[((size_t)b * OC + oc) * kN + n];
            if (relu) v = fmaxf(v, 0.0f);
            Y[((size_t)b * OC + oc) * kN + n] = v;
        }
    }
}

// ---------------- v_feat helpers: collapse global features to per-(b,c) bias ----------------
__global__ void gbias_kernel(const float* __restrict__ fuW, const float* __restrict__ gf,
                             float* __restrict__ gb)
{
    const int b = blockIdx.x, c = threadIdx.x;   // 128 threads
    const float* w = fuW + (size_t)c * (3 + kCG) + 3;
    const float* g = gf + b * kCG;
    float s = 0.0f;
    for (int j = 0; j < kCG; j++) s = fmaf(w[j], g[j], s);
    gb[b * kC + c] = s;
}

__global__ void vfeat_kernel(
    const float* __restrict__ fuW, const float* __restrict__ fub,
    const float* __restrict__ fug, const float* __restrict__ fube,
    const float* __restrict__ gb, const float* __restrict__ up_xyz,
    float* __restrict__ vf)
{
    const int b = blockIdx.z, c = blockIdx.y;
    const int n = blockIdx.x * 256 + threadIdx.x;
    const float w0 = fuW[c * (3 + kCG) + 0];
    const float w1 = fuW[c * (3 + kCG) + 1];
    const float w2 = fuW[c * (3 + kCG) + 2];
    const float x = up_xyz[(b * kN + n) * 3 + 0];
    const float y = up_xyz[(b * kN + n) * 3 + 1];
    const float z = up_xyz[(b * kN + n) * 3 + 2];
    float a = gb[b * kC + c] + fub[c] + w0 * x + w1 * y + w2 * z;
    const float rs = rsqrtf(1.0f + 1e-5f);
    a = fmaf(a, fug[c] * rs, fube[c]);
    vf[((size_t)b * kC + c) * kN + n] = fmaxf(a, 0.0f);
}

// ---------------- flash attention, 1 thread = 1 query row, fp32 ----------------
__global__ __launch_bounds__(128) void attn_kernel(
    const float* __restrict__ Q, const float* __restrict__ K,
    const float* __restrict__ V, float* __restrict__ O)
{
    __shared__ float Ks[kD][128];
    __shared__ float Vs[kD][128];
    const int bh  = blockIdx.y;             // b*H + h
    const int tid = threadIdx.x;
    const int n   = blockIdx.x * 128 + tid;

    const float* Qb = Q + (size_t)bh * kD * kN;
    const float* Kb = K + (size_t)bh * kD * kN;
    const float* Vb = V + (size_t)bh * kD * kN;

    const float ALPHA = 0.25f * 1.44269504088896340736f;  // D^-0.5 * log2(e)
    float q[kD], acc[kD];
#pragma unroll
    for (int d = 0; d < kD; d++) {
        q[d] = Qb[(size_t)d * kN + n] * ALPHA;
        acc[d] = 0.0f;
    }
    float m = -1e30f, l = 0.0f;

    for (int k0 = 0; k0 < kN; k0 += 128) {
        __syncthreads();
#pragma unroll
        for (int d = 0; d < kD; d++) {
            Ks[d][tid] = Kb[(size_t)d * kN + k0 + tid];
            Vs[d][tid] = Vb[(size_t)d * kN + k0 + tid];
        }
        __syncthreads();

#pragma unroll
        for (int jc = 0; jc < 8; jc++) {        // 16 keys per chunk
            float s[16];
#pragma unroll
            for (int g4 = 0; g4 < 4; g4++) {
                float s0 = 0.f, s1 = 0.f, s2 = 0.f, s3 = 0.f;
#pragma unroll
                for (int d = 0; d < kD; d++) {
                    const float4 kv = *(const float4*)&Ks[d][jc * 16 + g4 * 4];
                    s0 = fmaf(q[d], kv.x, s0);
                    s1 = fmaf(q[d], kv.y, s1);
                    s2 = fmaf(q[d], kv.z, s2);
                    s3 = fmaf(q[d], kv.w, s3);
                }
                s[g4 * 4 + 0] = s0; s[g4 * 4 + 1] = s1;
                s[g4 * 4 + 2] = s2; s[g4 * 4 + 3] = s3;
            }
            float mt = m;
#pragma unroll
            for (int j = 0; j < 16; j++) mt = fmaxf(mt, s[j]);
            const float r = exp2p(m - mt);
            m = mt;
            float psum = 0.0f;
#pragma unroll
            for (int j = 0; j < 16; j++) { s[j] = exp2p(s[j] - m); psum += s[j]; }
            l = fmaf(l, r, psum);
#pragma unroll
            for (int d = 0; d < kD; d++) acc[d] *= r;
#pragma unroll
            for (int g4 = 0; g4 < 4; g4++) {
#pragma unroll
                for (int d = 0; d < kD; d++) {
                    const float4 vv = *(const float4*)&Vs[d][jc * 16 + g4 * 4];
                    acc[d] = fmaf(s[g4 * 4 + 0], vv.x, acc[d]);
                    acc[d] = fmaf(s[g4 * 4 + 1], vv.y, acc[d]);
                    acc[d] = fmaf(s[g4 * 4 + 2], vv.z, acc[d]);
                    acc[d] = fmaf(s[g4 * 4 + 3], vv.w, acc[d]);
                }
            }
        }
    }

    const float inv = 1.0f / l;
    float* Ob = O + (size_t)bh * kD * kN;
#pragma unroll
    for (int d = 0; d < kD; d++) Ob[(size_t)d * kN + n] = acc[d] * inv;
}

// ---------------- launch ----------------
extern "C" void kernel_launch(void* const* d_in, const int* in_sizes, int n_in,
                              void* d_out, int out_size)
{
    const float* up_xyz   = (const float*)d_in[0];
    const float* xyz      = (const float*)d_in[1];
    const float* features = (const float*)d_in[2];
    const float* gfeat    = (const float*)d_in[3];
    const float* fp1_W = (const float*)d_in[4];
    const float* fp1_b = (const float*)d_in[5];
    const float* fp1_g = (const float*)d_in[6];
    const float* fp1_be= (const float*)d_in[7];
    const float* fp2_W = (const float*)d_in[8];
    const float* fp2_b = (const float*)d_in[9];
    const float* fp2_g = (const float*)d_in[10];
    const float* fp2_be= (const float*)d_in[11];
    const float* qm_W  = (const float*)d_in[12];
    const float* qm_b  = (const float*)d_in[13];
    const float* qm_g  = (const float*)d_in[14];
    const float* qm_be = (const float*)d_in[15];
    const float* fu_W  = (const float*)d_in[16];
    const float* fu_b  = (const float*)d_in[17];
    const float* fu_g  = (const float*)d_in[18];
    const float* fu_be = (const float*)d_in[19];
    const float* Wq    = (const float*)d_in[20];
    const float* Wk    = (const float*)d_in[21];
    const float* Wv    = (const float*)d_in[22];
    const float* Wp    = (const float*)d_in[23];
    const float* bp    = (const float*)d_in[24];
    const float* om_W  = (const float*)d_in[25];
    const float* om_b  = (const float*)d_in[26];
    const float* om_g  = (const float*)d_in[27];
    const float* om_be = (const float*)d_in[28];

    float *interp, *h1, *nf, *qf, *vf, *Q, *K, *V, *O, *y, *gb, *w;
    int* idx;
    cudaGetSymbolAddress((void**)&interp, g_interp);
    cudaGetSymbolAddress((void**)&h1,     g_h1);
    cudaGetSymbolAddress((void**)&nf,     g_nf);
    cudaGetSymbolAddress((void**)&qf,     g_qf);
    cudaGetSymbolAddress((void**)&vf,     g_vf);
    cudaGetSymbolAddress((void**)&Q,      g_Q);
    cudaGetSymbolAddress((void**)&K,      g_K);
    cudaGetSymbolAddress((void**)&V,      g_V);
    cudaGetSymbolAddress((void**)&O,      g_O);
    cudaGetSymbolAddress((void**)&y,      g_y);
    cudaGetSymbolAddress((void**)&gb,     g_gb);
    cudaGetSymbolAddress((void**)&idx,    g_idx);
    cudaGetSymbolAddress((void**)&w,      g_w);

    // 1) three_nn + weights
    knn_kernel<<<dim3(kN / 256, kB), 256>>>(up_xyz, xyz, idx, w);
    // 2) inverse-distance interpolation -> (B,256,N)
    interp_kernel<<<dim3(kN / 256, kCIN, kB), 256>>>(features, idx, w, interp);
    // 3) fp mlp: CBL 256->256, CBL 256->128
    gemm_cbl<<<dim3(kN / 64, kCIN / 64, kB), 256>>>(fp1_W, interp, h1,
                                                    fp1_b, fp1_g, fp1_be, nullptr, kCIN, kCIN, 1);
    gemm_cbl<<<dim3(kN / 64, kCFP / 64, kB), 256>>>(fp2_W, h1, nf,
                                                    fp2_b, fp2_g, fp2_be, nullptr, kCFP, kCIN, 1);
    // 4) q_feat = CBL 128->128
    gemm_cbl<<<dim3(kN / 64, kC / 64, kB), 256>>>(qm_W, nf, qf,
                                                  qm_b, qm_g, qm_be, nullptr, kC, kCFP, 1);
    // 5) v_feat via collapsed global-feature bias
    gbias_kernel<<<kB, kC>>>(fu_W, gfeat, gb);
    vfeat_kernel<<<dim3(kN / 256, kC, kB), 256>>>(fu_W, fu_b, fu_g, fu_be, gb, up_xyz, vf);
    // 6) Q, K, V projections (no epilogue)
    gemm_cbl<<<dim3(kN / 64, kC / 64, kB), 256>>>(Wq, qf, Q, nullptr, nullptr, nullptr, nullptr, kC, kC, 0);
    gemm_cbl<<<dim3(kN / 64, kC / 64, kB), 256>>>(Wk, vf, K, nullptr, nullptr, nullptr, nullptr, kC, kC, 0);
    gemm_cbl<<<dim3(kN / 64, kC / 64, kB), 256>>>(Wv, vf, V, nullptr, nullptr, nullptr, nullptr, kC, kC, 0);
    // 7) attention
    attn_kernel<<<dim3(kN / 128, kB * kH), 128>>>(Q, K, V, O);
    // 8) proj + residual add (y = qf + Wp@O + bp)
    gemm_cbl<<<dim3(kN / 64, kC / 64, kB), 256>>>(Wp, O, y, bp, nullptr, nullptr, qf, kC, kC, 0);
    // 9) out = CBL(y)
    gemm_cbl<<<dim3(kN / 64, kC / 64, kB), 256>>>(om_W, y, (float*)d_out,
                                                  om_b, om_g, om_be, nullptr, kC, kC, 1);
}

// round 3
// speedup vs baseline: 1.4510x; 1.4510x over previous
#include <cuda_runtime.h>
#include <math.h>

// ---------------- problem constants ----------------
constexpr int kB   = 8;
constexpr int kN   = 2048;
constexpr int kM   = 512;
constexpr int kCIN = 256;
constexpr int kCFP = 128;
constexpr int kC   = 128;   // C_OUT
constexpr int kCG  = 512;
constexpr int kH   = 8;
constexpr int kD   = 16;    // head dim

// ---------------- scratch (no allocation allowed) ----------------
__device__ float g_interp[kB * kCIN * kN];
__device__ float g_h1    [kB * kCIN * kN];
__device__ float g_nf    [kB * kCFP * kN];
__device__ float g_qf    [kB * kC   * kN];
__device__ float g_vf    [kB * kC   * kN];
__device__ float g_Q     [kB * kC   * kN];
__device__ float g_K     [kB * kC   * kN];
__device__ float g_V     [kB * kC   * kN];
__device__ float g_O     [kB * kC   * kN];
__device__ float g_y     [kB * kC   * kN];
__device__ float g_gb    [kB * kC];
__device__ int   g_idx   [kB * kN * 3];
__device__ float g_w     [kB * kN * 3];

// ---------------- packed f32x2 helpers (Blackwell FFMA2) ----------------
__device__ __forceinline__ void ffma2(float2& d, float2 a, float2 b) {
    asm("fma.rn.f32x2 %0, %1, %2, %0;"
        : "+l"(reinterpret_cast<unsigned long long&>(d))
        : "l"(reinterpret_cast<unsigned long long&>(a)),
          "l"(reinterpret_cast<unsigned long long&>(b)));
}
__device__ __forceinline__ void fmul2(float2& d, float2 a) {
    asm("mul.rn.f32x2 %0, %0, %1;"
        : "+l"(reinterpret_cast<unsigned long long&>(d))
        : "l"(reinterpret_cast<unsigned long long&>(a)));
}
__device__ __forceinline__ float ex2(float x) {
    float y;
    asm("ex2.approx.f32 %0, %1;" : "=f"(y) : "f"(x));
    return y;
}

// ---------------- three_nn ----------------
__global__ __launch_bounds__(256) void knn_kernel(
    const float* __restrict__ up_xyz, const float* __restrict__ xyz,
    int* __restrict__ idxo, float* __restrict__ wo)
{
    __shared__ float sx[kM * 3];
    const int b = blockIdx.y;
    for (int i = threadIdx.x; i < kM * 3; i += 256) sx[i] = xyz[b * kM * 3 + i];
    __syncthreads();

    const int n = blockIdx.x * 256 + threadIdx.x;
    const float px = up_xyz[(b * kN + n) * 3 + 0];
    const float py = up_xyz[(b * kN + n) * 3 + 1];
    const float pz = up_xyz[(b * kN + n) * 3 + 2];

    float d0 = 1e30f, d1 = 1e30f, d2 = 1e30f;
    int   i0 = 0,     i1 = 0,     i2 = 0;
    for (int m = 0; m < kM; m++) {
        float dx = sx[m * 3 + 0] - px;
        float dy = sx[m * 3 + 1] - py;
        float dz = sx[m * 3 + 2] - pz;
        float d  = dx * dx + dy * dy + dz * dz;
        if (d < d2) {
            if (d < d1) {
                if (d < d0) { d2 = d1; i2 = i1; d1 = d0; i1 = i0; d0 = d; i0 = m; }
                else        { d2 = d1; i2 = i1; d1 = d;  i1 = m; }
            } else          { d2 = d;  i2 = m; }
        }
    }
    d0 = fmaxf(d0, 1e-10f); d1 = fmaxf(d1, 1e-10f); d2 = fmaxf(d2, 1e-10f);
    float r0 = 1.0f / d0, r1 = 1.0f / d1, r2 = 1.0f / d2;
    float s  = r0 + r1 + r2;
    const int base = (b * kN + n) * 3;
    idxo[base] = i0; idxo[base + 1] = i1; idxo[base + 2] = i2;
    wo[base] = r0 / s; wo[base + 1] = r1 / s; wo[base + 2] = r2 / s;
}

// ---------------- inverse-distance interpolation ----------------
__global__ void interp_kernel(
    const float* __restrict__ feat, const int* __restrict__ idx3,
    const float* __restrict__ w3, float* __restrict__ out)
{
    const int b = blockIdx.z, c = blockIdx.y;
    const int n = blockIdx.x * 256 + threadIdx.x;
    const float* f = feat + ((size_t)b * kCIN + c) * kM;
    const int base = (b * kN + n) * 3;
    const int j0 = idx3[base], j1 = idx3[base + 1], j2 = idx3[base + 2];
    const float w0 = w3[base], w1 = w3[base + 1], w2 = w3[base + 2];
    out[((size_t)b * kCIN + c) * kN + n] = w0 * f[j0] + w1 * f[j1] + w2 * f[j2];
}

// ---------------- 128x128 GEMM tile body, 8x8/thread, packed FFMA2 ----------------
// W: [128][IC] (already offset to oc0), Xb: [IC][kN] batch slice,
// Yb: [128][kN] (already offset), epilogue params already offset to oc0.
__device__ __forceinline__ void gemm_tile(
    const float* __restrict__ W, const float* __restrict__ Xb, float* __restrict__ Yb,
    int IC, int n0,
    const float* bias, const float* gamma, const float* beta,
    const float* addB, int relu,
    float (*Ws)[132], float (*Xs)[132])
{
    const int tid = threadIdx.x;
    const int tx = tid & 15, ty = tid >> 4;

    float2 acc[8][4];
#pragma unroll
    for (int i = 0; i < 8; i++)
#pragma unroll
        for (int j = 0; j < 4; j++) acc[i][j] = make_float2(0.f, 0.f);

    for (int k0 = 0; k0 < IC; k0 += 16) {
#pragma unroll
        for (int r = 0; r < 2; r++) {
            const int v  = r * 256 + tid;
            const int oc = v >> 2, kq = v & 3;
            const float4 w4 = *(const float4*)&W[(size_t)oc * IC + k0 + kq * 4];
            Ws[kq * 4 + 0][oc] = w4.x;
            Ws[kq * 4 + 1][oc] = w4.y;
            Ws[kq * 4 + 2][oc] = w4.z;
            Ws[kq * 4 + 3][oc] = w4.w;
            const int k = v >> 5, nf = (v & 31) * 4;
            *(float4*)&Xs[k][nf] = *(const float4*)&Xb[(size_t)(k0 + k) * kN + n0 + nf];
        }
        __syncthreads();
#pragma unroll
        for (int kk = 0; kk < 16; kk++) {
            const float4 x0 = *(const float4*)&Xs[kk][tx * 8];
            const float4 x1 = *(const float4*)&Xs[kk][tx * 8 + 4];
            const float4 w0 = *(const float4*)&Ws[kk][ty * 8];
            const float4 w1 = *(const float4*)&Ws[kk][ty * 8 + 4];
            float2 xp[4] = {{x0.x, x0.y}, {x0.z, x0.w}, {x1.x, x1.y}, {x1.z, x1.w}};
            float  wr[8] = {w0.x, w0.y, w0.z, w0.w, w1.x, w1.y, w1.z, w1.w};
#pragma unroll
            for (int i = 0; i < 8; i++) {
                const float2 wd = make_float2(wr[i], wr[i]);
#pragma unroll
                for (int j = 0; j < 4; j++) ffma2(acc[i][j], wd, xp[j]);
            }
        }
        __syncthreads();
    }

    const float rs = rsqrtf(1.0f + 1e-5f);
#pragma unroll
    for (int i = 0; i < 8; i++) {
        const int oc = ty * 8 + i;
        const float bi = bias  ? bias[oc]       : 0.0f;
        const float sc = gamma ? gamma[oc] * rs : 1.0f;
        const float bb = gamma ? beta[oc]       : 0.0f;
        float o[8] = {acc[i][0].x, acc[i][0].y, acc[i][1].x, acc[i][1].y,
                      acc[i][2].x, acc[i][2].y, acc[i][3].x, acc[i][3].y};
#pragma unroll
        for (int j = 0; j < 8; j++) {
            float v = fmaf(o[j] + bi, sc, bb);
            if (addB) v += addB[(size_t)oc * kN + n0 + tx * 8 + j];
            if (relu) v = fmaxf(v, 0.0f);
            o[j] = v;
        }
        *(float4*)&Yb[(size_t)oc * kN + n0 + tx * 8]     = make_float4(o[0], o[1], o[2], o[3]);
        *(float4*)&Yb[(size_t)oc * kN + n0 + tx * 8 + 4] = make_float4(o[4], o[5], o[6], o[7]);
    }
}

__global__ __launch_bounds__(256, 2) void gemm128(
    const float* __restrict__ W, const float* __restrict__ X, float* __restrict__ Y,
    const float* __restrict__ bias, const float* __restrict__ gamma,
    const float* __restrict__ beta, const float* __restrict__ add,
    int OC, int IC, int relu)
{
    __shared__ float Ws[16][132];
    __shared__ float Xs[16][132];
    const int b   = blockIdx.z;
    const int n0  = blockIdx.x * 128;
    const int oc0 = blockIdx.y * 128;
    gemm_tile(W + (size_t)oc0 * IC,
              X + (size_t)b * IC * kN,
              Y + ((size_t)b * OC + oc0) * kN,
              IC, n0,
              bias  ? bias  + oc0 : nullptr,
              gamma ? gamma + oc0 : nullptr,
              beta  ? beta  + oc0 : nullptr,
              add   ? add + ((size_t)b * OC + oc0) * kN : nullptr,
              relu, Ws, Xs);
}

// fused Q/K/V projection: blockIdx.y selects which GEMM
__global__ __launch_bounds__(256, 2) void qkv128(
    const float* __restrict__ Wq, const float* __restrict__ Wk, const float* __restrict__ Wv,
    const float* __restrict__ qf, const float* __restrict__ vf,
    float* __restrict__ Q, float* __restrict__ K, float* __restrict__ V)
{
    __shared__ float Ws[16][132];
    __shared__ float Xs[16][132];
    const int b = blockIdx.z;
    const int y = blockIdx.y;
    const float* W = (y == 0) ? Wq : (y == 1) ? Wk : Wv;
    const float* X = ((y == 0) ? qf : vf) + (size_t)b * kC * kN;
    float*       Y = ((y == 0) ? Q : (y == 1) ? K : V) + (size_t)b * kC * kN;
    gemm_tile(W, X, Y, kC, blockIdx.x * 128,
              nullptr, nullptr, nullptr, nullptr, 0, Ws, Xs);
}

// ---------------- v_feat helpers ----------------
__global__ void gbias_kernel(const float* __restrict__ fuW, const float* __restrict__ gf,
                             float* __restrict__ gb)
{
    const int b = blockIdx.x, c = threadIdx.x;
    const float* w = fuW + (size_t)c * (3 + kCG) + 3;
    const float* g = gf + b * kCG;
    float s = 0.0f;
    for (int j = 0; j < kCG; j++) s = fmaf(w[j], g[j], s);
    gb[b * kC + c] = s;
}

__global__ void vfeat_kernel(
    const float* __restrict__ fuW, const float* __restrict__ fub,
    const float* __restrict__ fug, const float* __restrict__ fube,
    const float* __restrict__ gb, const float* __restrict__ up_xyz,
    float* __restrict__ vf)
{
    const int b = blockIdx.z, c = blockIdx.y;
    const int n = blockIdx.x * 256 + threadIdx.x;
    const float w0 = fuW[c * (3 + kCG) + 0];
    const float w1 = fuW[c * (3 + kCG) + 1];
    const float w2 = fuW[c * (3 + kCG) + 2];
    const float x = up_xyz[(b * kN + n) * 3 + 0];
    const float y = up_xyz[(b * kN + n) * 3 + 1];
    const float z = up_xyz[(b * kN + n) * 3 + 2];
    float a = gb[b * kC + c] + fub[c] + w0 * x + w1 * y + w2 * z;
    const float rs = rsqrtf(1.0f + 1e-5f);
    a = fmaf(a, fug[c] * rs, fube[c]);
    vf[((size_t)b * kC + c) * kN + n] = fmaxf(a, 0.0f);
}

// ---------------- flash attention, packed FFMA2 + MUFU ex2 ----------------
__global__ __launch_bounds__(128) void attn2(
    const float* __restrict__ Q, const float* __restrict__ K,
    const float* __restrict__ V, float* __restrict__ O)
{
    __shared__ float Ks[kD][128];
    __shared__ float Vs[8][256];    // [dpair][2*key + half]: Vs[dp][2j+h] = V[2dp+h][j]
    const int bh  = blockIdx.y;
    const int tid = threadIdx.x;
    const int n   = blockIdx.x * 128 + tid;

    const float* Qb = Q + (size_t)bh * kD * kN;
    const float* Kb = K + (size_t)bh * kD * kN;
    const float* Vb = V + (size_t)bh * kD * kN;

    const float ALPHA = 0.25f * 1.44269504088896340736f;  // D^-0.5 * log2(e)
    float2 q2[kD];
#pragma unroll
    for (int d = 0; d < kD; d++) {
        const float qv = Qb[(size_t)d * kN + n] * ALPHA;
        q2[d] = make_float2(qv, qv);
    }
    float2 acc[8];
#pragma unroll
    for (int dp = 0; dp < 8; dp++) acc[dp] = make_float2(0.f, 0.f);
    float m = -1e30f, l = 0.0f;

    for (int k0 = 0; k0 < kN; k0 += 128) {
        __syncthreads();
#pragma unroll
        for (int d = 0; d < kD; d++) {
            Ks[d][tid] = Kb[(size_t)d * kN + k0 + tid];
            Vs[d >> 1][2 * tid + (d & 1)] = Vb[(size_t)d * kN + k0 + tid];
        }
        __syncthreads();

#pragma unroll 1
        for (int jc = 0; jc < 8; jc++) {        // 16 keys per chunk
            float s[16];
#pragma unroll
            for (int g = 0; g < 4; g++) {       // 4 keys per group, packed in pairs
                float2 sa = make_float2(0.f, 0.f);
                float2 sb = make_float2(0.f, 0.f);
#pragma unroll
                for (int d = 0; d < kD; d++) {
                    const float4 k4 = *(const float4*)&Ks[d][jc * 16 + g * 4];
                    ffma2(sa, q2[d], make_float2(k4.x, k4.y));
                    ffma2(sb, q2[d], make_float2(k4.z, k4.w));
                }
                s[g * 4 + 0] = sa.x; s[g * 4 + 1] = sa.y;
                s[g * 4 + 2] = sb.x; s[g * 4 + 3] = sb.y;
            }
            float mt = m;
#pragma unroll
            for (int j = 0; j < 16; j++) mt = fmaxf(mt, s[j]);
            const float r = ex2(m - mt);
            m = mt;
            const float2 rd = make_float2(r, r);
#pragma unroll
            for (int dp = 0; dp < 8; dp++) fmul2(acc[dp], rd);
            l *= r;

#pragma unroll
            for (int jp = 0; jp < 8; jp++) {    // key pairs
                const int j0 = jc * 16 + jp * 2;
                const float p0 = ex2(s[jp * 2 + 0] - mt);
                const float p1 = ex2(s[jp * 2 + 1] - mt);
                l += p0; l += p1;
                const float2 pd0 = make_float2(p0, p0);
                const float2 pd1 = make_float2(p1, p1);
#pragma unroll
                for (int dp = 0; dp < 8; dp++) {
                    const float4 v4 = *(const float4*)&Vs[dp][2 * j0];
                    ffma2(acc[dp], pd0, make_float2(v4.x, v4.y));
                    ffma2(acc[dp], pd1, make_float2(v4.z, v4.w));
                }
            }
        }
    }

    const float inv = 1.0f / l;
    float* Ob = O + (size_t)bh * kD * kN;
#pragma unroll
    for (int dp = 0; dp < 8; dp++) {
        Ob[(size_t)(2 * dp + 0) * kN + n] = acc[dp].x * inv;
        Ob[(size_t)(2 * dp + 1) * kN + n] = acc[dp].y * inv;
    }
}

// ---------------- launch ----------------
extern "C" void kernel_launch(void* const* d_in, const int* in_sizes, int n_in,
                              void* d_out, int out_size)
{
    const float* up_xyz   = (const float*)d_in[0];
    const float* xyz      = (const float*)d_in[1];
    const float* features = (const float*)d_in[2];
    const float* gfeat    = (const float*)d_in[3];
    const float* fp1_W = (const float*)d_in[4];
    const float* fp1_b = (const float*)d_in[5];
    const float* fp1_g = (const float*)d_in[6];
    const float* fp1_be= (const float*)d_in[7];
    const float* fp2_W = (const float*)d_in[8];
    const float* fp2_b = (const float*)d_in[9];
    const float* fp2_g = (const float*)d_in[10];
    const float* fp2_be= (const float*)d_in[11];
    const float* qm_W  = (const float*)d_in[12];
    const float* qm_b  = (const float*)d_in[13];
    const float* qm_g  = (const float*)d_in[14];
    const float* qm_be = (const float*)d_in[15];
    const float* fu_W  = (const float*)d_in[16];
    const float* fu_b  = (const float*)d_in[17];
    const float* fu_g  = (const float*)d_in[18];
    const float* fu_be = (const float*)d_in[19];
    const float* Wq    = (const float*)d_in[20];
    const float* Wk    = (const float*)d_in[21];
    const float* Wv    = (const float*)d_in[22];
    const float* Wp    = (const float*)d_in[23];
    const float* bp    = (const float*)d_in[24];
    const float* om_W  = (const float*)d_in[25];
    const float* om_b  = (const float*)d_in[26];
    const float* om_g  = (const float*)d_in[27];
    const float* om_be = (const float*)d_in[28];

    float *interp, *h1, *nf, *qf, *vf, *Q, *K, *V, *O, *y, *gb, *w;
    int* idx;
    cudaGetSymbolAddress((void**)&interp, g_interp);
    cudaGetSymbolAddress((void**)&h1,     g_h1);
    cudaGetSymbolAddress((void**)&nf,     g_nf);
    cudaGetSymbolAddress((void**)&qf,     g_qf);
    cudaGetSymbolAddress((void**)&vf,     g_vf);
    cudaGetSymbolAddress((void**)&Q,      g_Q);
    cudaGetSymbolAddress((void**)&K,      g_K);
    cudaGetSymbolAddress((void**)&V,      g_V);
    cudaGetSymbolAddress((void**)&O,      g_O);
    cudaGetSymbolAddress((void**)&y,      g_y);
    cudaGetSymbolAddress((void**)&gb,     g_gb);
    cudaGetSymbolAddress((void**)&idx,    g_idx);
    cudaGetSymbolAddress((void**)&w,      g_w);

    // 1) three_nn + weights
    knn_kernel<<<dim3(kN / 256, kB), 256>>>(up_xyz, xyz, idx, w);
    // 2) inverse-distance interpolation -> (B,256,N)
    interp_kernel<<<dim3(kN / 256, kCIN, kB), 256>>>(features, idx, w, interp);
    // 3) fp mlp: CBL 256->256, CBL 256->128
    gemm128<<<dim3(kN / 128, kCIN / 128, kB), 256>>>(fp1_W, interp, h1,
                                                     fp1_b, fp1_g, fp1_be, nullptr, kCIN, kCIN, 1);
    gemm128<<<dim3(kN / 128, 1, kB), 256>>>(fp2_W, h1, nf,
                                            fp2_b, fp2_g, fp2_be, nullptr, kCFP, kCIN, 1);
    // 4) q_feat = CBL 128->128
    gemm128<<<dim3(kN / 128, 1, kB), 256>>>(qm_W, nf, qf,
                                            qm_b, qm_g, qm_be, nullptr, kC, kCFP, 1);
    // 5) v_feat via collapsed global-feature bias
    gbias_kernel<<<kB, kC>>>(fu_W, gfeat, gb);
    vfeat_kernel<<<dim3(kN / 256, kC, kB), 256>>>(fu_W, fu_b, fu_g, fu_be, gb, up_xyz, vf);
    // 6) fused Q/K/V projections
    qkv128<<<dim3(kN / 128, 3, kB), 256>>>(Wq, Wk, Wv, qf, vf, Q, K, V);
    // 7) attention
    attn2<<<dim3(kN / 128, kB * kH), 128>>>(Q, K, V, O);
    // 8) proj + residual add (y = qf + Wp@O + bp)
    gemm128<<<dim3(kN / 128, 1, kB), 256>>>(Wp, O, y, bp, nullptr, nullptr, qf, kC, kC, 0);
    // 9) out = CBL(y)
    gemm128<<<dim3(kN / 128, 1, kB), 256>>>(om_W, y, (float*)d_out,
                                            om_b, om_g, om_be, nullptr, kC, kC, 1);
}